// round 6
// baseline (speedup 1.0000x reference)
#include <cuda_runtime.h>
#include <cstdint>

#define N_NODES 50000
#define DIM     64
#define CHUNKS  (DIM / 4)    // 16 float4 per row
#define TPE     8            // 8 threads/edge: one 128B line per load slot

// Accumulator [N_NODES, 16] float4 = 12.8 MB (L2-resident), 16B-aligned by type.
__device__ float4 g_Mv[(size_t)N_NODES * CHUNKS];

__device__ __forceinline__ long long load_idx(const void* base, long long i, int is64) {
    if (is64) return __ldg(((const long long*)base) + i);
    return (long long)__ldg(((const int*)base) + i);
}

// Broadcast a 64-bit value from lane 0 of each 8-lane segment.
__device__ __forceinline__ long long bcast8(long long v) {
    return __shfl_sync(0xFFFFFFFFu, v, 0, 8);
}

// Per-block dtype probe: thread 0 reads 8 entries of rev as int64; if any is
// outside [0,E) the storage must be int32 (fused hi word != 0). False-accept
// probability for int32 data: (1/50000)^8 ~ 0. Result broadcast via shared.
__device__ __forceinline__ int probe_is64(const void* rev, int E) {
    __shared__ int sh_is64;
    if (threadIdx.x == 0) {
        const long long* r64 = (const long long*)rev;
        int ok = 1;
        #pragma unroll
        for (int k = 0; k < 8; k++) {
            long long v = r64[k];
            if (v < 0 || v >= (long long)E) { ok = 0; break; }
        }
        sh_is64 = ok;
    }
    __syncthreads();
    return sh_is64;
}

// ---------------------------------------------------------------------------
// Kernel 1: scatter-add. 8 threads/edge, 2 float4 chunks each (c, c+8).
// Each warp load slot covers 4 edges x full 128B lines. One index LDG per
// edge-group (lane 0), shuffled to the other 7 lanes.
// red.global.add.v4.f32: one 16B L2-side reduction per chunk.
// ---------------------------------------------------------------------------
__global__ void scatter_kernel(const float4* __restrict__ M4,
                               const void* __restrict__ ei,
                               const void* __restrict__ rev,
                               int E) {
    int is64 = probe_is64(rev, E);

    int t = blockIdx.x * blockDim.x + threadIdx.x;
    int e = t >> 3;
    int c = t & 7;
    if (e >= E) return;

    long long d = 0;
    if (c == 0) d = load_idx(ei, (long long)E + e, is64);   // dest
    d = bcast8(d);

    const float4* mrow = M4 + (size_t)e * CHUNKS;
    float4 v0 = __ldg(&mrow[c]);
    float4 v1 = __ldg(&mrow[c + 8]);

    float4* prow = g_Mv + (size_t)d * CHUNKS;
    asm volatile("red.global.add.v4.f32 [%0], {%1, %2, %3, %4};"
        :: "l"(__cvta_generic_to_global(prow + c)),
           "f"(v0.x), "f"(v0.y), "f"(v0.z), "f"(v0.w) : "memory");
    asm volatile("red.global.add.v4.f32 [%0], {%1, %2, %3, %4};"
        :: "l"(__cvta_generic_to_global(prow + c + 8)),
           "f"(v1.x), "f"(v1.y), "f"(v1.z), "f"(v1.w) : "memory");
}

// ---------------------------------------------------------------------------
// Kernel 2: out[e] = M_v[src[e]] - M[rev[e]]. 8 threads/edge, 2 chunks each.
// M_v: evict-normal (L2-resident). M[rev]: __ldcs evict-first.
// out: st.global.wt write-through -> single LTS transit, no L2 pollution.
// ---------------------------------------------------------------------------
__device__ __forceinline__ void stwt4(float4* p, float4 v) {
    asm volatile("st.global.wt.v4.f32 [%0], {%1, %2, %3, %4};"
        :: "l"(__cvta_generic_to_global(p)),
           "f"(v.x), "f"(v.y), "f"(v.z), "f"(v.w) : "memory");
}

__global__ void gather_kernel(const float4* __restrict__ M4,
                              const void* __restrict__ ei,
                              const void* __restrict__ rev,
                              float4* __restrict__ out,
                              int E) {
    int is64 = probe_is64(rev, E);

    int t = blockIdx.x * blockDim.x + threadIdx.x;
    int e = t >> 3;
    int c = t & 7;
    if (e >= E) return;

    long long s = 0, r = 0;
    if (c == 0) {
        s = load_idx(ei, e, is64);     // src
        r = load_idx(rev, e, is64);    // rev
    }
    s = bcast8(s);
    r = bcast8(r);

    const float4* arow = g_Mv + (size_t)s * CHUNKS;
    const float4* brow = M4 + (size_t)r * CHUNKS;

    float4 a0 = __ldg(&arow[c]);
    float4 a1 = __ldg(&arow[c + 8]);
    float4 b0 = __ldcs(&brow[c]);
    float4 b1 = __ldcs(&brow[c + 8]);

    float4 o0, o1;
    o0.x = a0.x - b0.x; o0.y = a0.y - b0.y; o0.z = a0.z - b0.z; o0.w = a0.w - b0.w;
    o1.x = a1.x - b1.x; o1.y = a1.y - b1.y; o1.z = a1.z - b1.z; o1.w = a1.w - b1.w;

    float4* orow = out + (size_t)e * CHUNKS;
    stwt4(&orow[c], o0);
    stwt4(&orow[c + 8], o1);
}

// ---------------------------------------------------------------------------
// Launcher. Inputs (metadata order):
//   d_in[0] = M          float32     [E, 64]
//   d_in[1] = edge_index int64/int32 [2, E]  (row0=src, row1=dest)
//   d_in[2] = rev_index  int64/int32 [E]
//   d_in[3] = dim_size   scalar (50000, unused)
// Output: float32 [E, 64]
// ---------------------------------------------------------------------------
extern "C" void kernel_launch(void* const* d_in, const int* in_sizes, int n_in,
                              void* d_out, int out_size) {
    const float4* M4   = (const float4*)d_in[0];
    const void*   ei   = d_in[1];
    const void*   rev  = d_in[2];
    float4*       out4 = (float4*)d_out;

    const int E = in_sizes[2];

    // 1) zero accumulator via memset node (full-bandwidth, no kernel launch)
    void* mv_ptr = nullptr;
    cudaGetSymbolAddress(&mv_ptr, g_Mv);
    cudaMemsetAsync(mv_ptr, 0, (size_t)N_NODES * CHUNKS * sizeof(float4));

    // 2) scatter-add
    {
        long long threads = (long long)E * TPE;
        int tpb = 256;
        int blocks = (int)((threads + tpb - 1) / tpb);
        scatter_kernel<<<blocks, tpb>>>(M4, ei, rev, E);
    }

    // 3) gather + subtract
    {
        long long threads = (long long)E * TPE;
        int tpb = 256;
        int blocks = (int)((threads + tpb - 1) / tpb);
        gather_kernel<<<blocks, tpb>>>(M4, ei, rev, out4, E);
    }
}

// round 7
// speedup vs baseline: 1.0227x; 1.0227x over previous
#include <cuda_runtime.h>
#include <cstdint>

#define N_NODES 50000
#define DIM     64
#define CHUNKS  (DIM / 4)    // 16 float4 per row
#define TPE     8            // 8 threads/edge: one full 128B line per load slot

// Accumulator [N_NODES, 16] float4 = 12.8 MB (L2-resident), 16B-aligned by type.
__device__ float4 g_Mv[(size_t)N_NODES * CHUNKS];

__device__ __forceinline__ long long load_idx(const void* base, long long i, int is64) {
    if (is64) return __ldg(((const long long*)base) + i);
    return (long long)__ldg(((const int*)base) + i);
}

// Broadcast a 64-bit value from lane 0 of each 8-lane segment.
__device__ __forceinline__ long long bcast8(long long v) {
    return __shfl_sync(0xFFFFFFFFu, v, 0, 8);
}

// Per-block dtype probe: thread 0 reads 8 entries of rev as int64; any value
// outside [0,E) means the storage is int32 (fused words). False-accept
// probability for int32 data ~ (2e-5)^8 ~ 0. Broadcast via shared.
__device__ __forceinline__ int probe_is64(const void* rev, int E) {
    __shared__ int sh_is64;
    if (threadIdx.x == 0) {
        const long long* r64 = (const long long*)rev;
        int ok = 1;
        #pragma unroll
        for (int k = 0; k < 8; k++) {
            long long v = r64[k];
            if (v < 0 || v >= (long long)E) { ok = 0; break; }
        }
        sh_is64 = ok;
    }
    __syncthreads();
    return sh_is64;
}

// ---------------------------------------------------------------------------
// Kernel 1: scatter-add. 8 threads/edge, 2 float4 chunks each (c, c+8).
// Coalesced full-line M reads; red.global.add.v4.f32 = 16B L2-side RED.
// ---------------------------------------------------------------------------
__global__ void scatter_kernel(const float4* __restrict__ M4,
                               const void* __restrict__ ei,
                               const void* __restrict__ rev,
                               int E) {
    int is64 = probe_is64(rev, E);

    int t = blockIdx.x * blockDim.x + threadIdx.x;
    int e = t >> 3;
    int c = t & 7;
    if (e >= E) return;

    long long d = 0;
    if (c == 0) d = load_idx(ei, (long long)E + e, is64);   // dest
    d = bcast8(d);

    const float4* mrow = M4 + (size_t)e * CHUNKS;
    float4 v0 = __ldg(&mrow[c]);
    float4 v1 = __ldg(&mrow[c + 8]);

    float4* prow = g_Mv + (size_t)d * CHUNKS;
    asm volatile("red.global.add.v4.f32 [%0], {%1, %2, %3, %4};"
        :: "l"(__cvta_generic_to_global(prow + c)),
           "f"(v0.x), "f"(v0.y), "f"(v0.z), "f"(v0.w) : "memory");
    asm volatile("red.global.add.v4.f32 [%0], {%1, %2, %3, %4};"
        :: "l"(__cvta_generic_to_global(prow + c + 8)),
           "f"(v1.x), "f"(v1.y), "f"(v1.z), "f"(v1.w) : "memory");
}

// ---------------------------------------------------------------------------
// Kernel 2: out[e] = M_v[src[e]] - M[rev[e]]. 8 threads/edge, 2 chunks each.
// M_v: __ldg (L2-resident, 16x reuse). M[rev]: __ldg evict-NORMAL to capture
// the ~37% duplicate-row reuse in the random rev index (rev has E draws over
// E rows -> 1-1/e unique). out: __stcs evict-first (write-once data).
// ---------------------------------------------------------------------------
__global__ void gather_kernel(const float4* __restrict__ M4,
                              const void* __restrict__ ei,
                              const void* __restrict__ rev,
                              float4* __restrict__ out,
                              int E) {
    int is64 = probe_is64(rev, E);

    int t = blockIdx.x * blockDim.x + threadIdx.x;
    int e = t >> 3;
    int c = t & 7;
    if (e >= E) return;

    long long s = 0, r = 0;
    if (c == 0) {
        s = load_idx(ei, e, is64);     // src
        r = load_idx(rev, e, is64);    // rev
    }
    s = bcast8(s);
    r = bcast8(r);

    const float4* arow = g_Mv + (size_t)s * CHUNKS;
    const float4* brow = M4 + (size_t)r * CHUNKS;

    float4 a0 = __ldg(&arow[c]);
    float4 a1 = __ldg(&arow[c + 8]);
    float4 b0 = __ldg(&brow[c]);
    float4 b1 = __ldg(&brow[c + 8]);

    float4 o0, o1;
    o0.x = a0.x - b0.x; o0.y = a0.y - b0.y; o0.z = a0.z - b0.z; o0.w = a0.w - b0.w;
    o1.x = a1.x - b1.x; o1.y = a1.y - b1.y; o1.z = a1.z - b1.z; o1.w = a1.w - b1.w;

    float4* orow = out + (size_t)e * CHUNKS;
    __stcs(&orow[c], o0);
    __stcs(&orow[c + 8], o1);
}

// ---------------------------------------------------------------------------
// Launcher. Inputs (metadata order):
//   d_in[0] = M          float32     [E, 64]
//   d_in[1] = edge_index int64/int32 [2, E]  (row0=src, row1=dest)
//   d_in[2] = rev_index  int64/int32 [E]
//   d_in[3] = dim_size   scalar (50000, unused)
// Output: float32 [E, 64]
// ---------------------------------------------------------------------------
extern "C" void kernel_launch(void* const* d_in, const int* in_sizes, int n_in,
                              void* d_out, int out_size) {
    const float4* M4   = (const float4*)d_in[0];
    const void*   ei   = d_in[1];
    const void*   rev  = d_in[2];
    float4*       out4 = (float4*)d_out;

    const int E = in_sizes[2];

    // 1) zero accumulator via memset node (no kernel launch overhead)
    void* mv_ptr = nullptr;
    cudaGetSymbolAddress(&mv_ptr, g_Mv);
    cudaMemsetAsync(mv_ptr, 0, (size_t)N_NODES * CHUNKS * sizeof(float4));

    // 2) scatter-add
    {
        long long threads = (long long)E * TPE;
        int tpb = 256;
        int blocks = (int)((threads + tpb - 1) / tpb);
        scatter_kernel<<<blocks, tpb>>>(M4, ei, rev, E);
    }

    // 3) gather + subtract
    {
        long long threads = (long long)E * TPE;
        int tpb = 256;
        int blocks = (int)((threads + tpb - 1) / tpb);
        gather_kernel<<<blocks, tpb>>>(M4, ei, rev, out4, E);
    }
}

// round 8
// speedup vs baseline: 1.0733x; 1.0495x over previous
#include <cuda_runtime.h>
#include <cstdint>

#define N_NODES 50000
#define DIM     64
#define CHUNKS  (DIM / 4)    // 16 float4 per row
#define TPE     8            // 8 threads per edge-slot; full 128B line coalescing
#define EPT     2            // edges per thread in gather

// Accumulator [N_NODES, 16] float4 = 12.8 MB (L2-resident), 16B-aligned by type.
__device__ float4 g_Mv[(size_t)N_NODES * CHUNKS];

__device__ __forceinline__ long long load_idx(const void* base, long long i, int is64) {
    if (is64) return __ldg(((const long long*)base) + i);
    return (long long)__ldg(((const int*)base) + i);
}

__device__ __forceinline__ long long bcast8(long long v) {
    return __shfl_sync(0xFFFFFFFFu, v, 0, 8);
}

// Per-block dtype probe (thread 0 checks 8 entries, broadcast via shared).
__device__ __forceinline__ int probe_is64(const void* rev, int E) {
    __shared__ int sh_is64;
    if (threadIdx.x == 0) {
        const long long* r64 = (const long long*)rev;
        int ok = 1;
        #pragma unroll
        for (int k = 0; k < 8; k++) {
            long long v = r64[k];
            if (v < 0 || v >= (long long)E) { ok = 0; break; }
        }
        sh_is64 = ok;
    }
    __syncthreads();
    return sh_is64;
}

// ---------------------------------------------------------------------------
// Kernel 1: scatter-add. 8 threads/edge, 2 float4 chunks each.
// M read: __ldcs evict-first -- streaming M must NOT evict the L2-resident
// M_v accumulator (12.8MB, hit by 12.8M REDs). RED.v4 = 16B L2-side add.
// ---------------------------------------------------------------------------
__global__ void scatter_kernel(const float4* __restrict__ M4,
                               const void* __restrict__ ei,
                               const void* __restrict__ rev,
                               int E) {
    int is64 = probe_is64(rev, E);

    int t = blockIdx.x * blockDim.x + threadIdx.x;
    int e = t >> 3;
    int c = t & 7;
    if (e >= E) return;

    long long d = 0;
    if (c == 0) d = load_idx(ei, (long long)E + e, is64);   // dest
    d = bcast8(d);

    const float4* mrow = M4 + (size_t)e * CHUNKS;
    float4 v0 = __ldcs(&mrow[c]);
    float4 v1 = __ldcs(&mrow[c + 8]);

    float4* prow = g_Mv + (size_t)d * CHUNKS;
    asm volatile("red.global.add.v4.f32 [%0], {%1, %2, %3, %4};"
        :: "l"(__cvta_generic_to_global(prow + c)),
           "f"(v0.x), "f"(v0.y), "f"(v0.z), "f"(v0.w) : "memory");
    asm volatile("red.global.add.v4.f32 [%0], {%1, %2, %3, %4};"
        :: "l"(__cvta_generic_to_global(prow + c + 8)),
           "f"(v1.x), "f"(v1.y), "f"(v1.z), "f"(v1.w) : "memory");
}

// ---------------------------------------------------------------------------
// Kernel 2: out[e] = M_v[src[e]] - M[rev[e]].
// 8 threads per edge-slot, each thread processes 2 edges (e and e+1 within a
// paired slot) -> 8 independent loads in flight per thread to saturate DRAM.
// M_v: __ldg (L2-resident). M[rev]: __ldg. out: __stcs (write-once).
// ---------------------------------------------------------------------------
__global__ void gather_kernel(const float4* __restrict__ M4,
                              const void* __restrict__ ei,
                              const void* __restrict__ rev,
                              float4* __restrict__ out,
                              int E) {
    int is64 = probe_is64(rev, E);

    int t = blockIdx.x * blockDim.x + threadIdx.x;
    long long g = (long long)(t >> 3) * EPT;     // first edge of this thread's pair
    int c = t & 7;

    long long e0 = g;
    long long e1 = g + 1;
    bool p0 = e0 < E;
    bool p1 = e1 < E;
    if (!p0) return;

    long long s0 = 0, r0 = 0, s1 = 0, r1 = 0;
    if (c == 0) {
        s0 = load_idx(ei, e0, is64);
        r0 = load_idx(rev, e0, is64);
        if (p1) {
            s1 = load_idx(ei, e1, is64);
            r1 = load_idx(rev, e1, is64);
        }
    }
    s0 = bcast8(s0); r0 = bcast8(r0);
    s1 = bcast8(s1); r1 = bcast8(r1);

    const float4* arow0 = g_Mv + (size_t)s0 * CHUNKS;
    const float4* brow0 = M4 + (size_t)r0 * CHUNKS;

    // issue all independent loads up front
    float4 a00 = __ldg(&arow0[c]);
    float4 a01 = __ldg(&arow0[c + 8]);
    float4 b00 = __ldg(&brow0[c]);
    float4 b01 = __ldg(&brow0[c + 8]);

    float4 a10, a11, b10, b11;
    if (p1) {
        const float4* arow1 = g_Mv + (size_t)s1 * CHUNKS;
        const float4* brow1 = M4 + (size_t)r1 * CHUNKS;
        a10 = __ldg(&arow1[c]);
        a11 = __ldg(&arow1[c + 8]);
        b10 = __ldg(&brow1[c]);
        b11 = __ldg(&brow1[c + 8]);
    }

    float4 o;
    float4* orow0 = out + (size_t)e0 * CHUNKS;
    o.x = a00.x - b00.x; o.y = a00.y - b00.y; o.z = a00.z - b00.z; o.w = a00.w - b00.w;
    __stcs(&orow0[c], o);
    o.x = a01.x - b01.x; o.y = a01.y - b01.y; o.z = a01.z - b01.z; o.w = a01.w - b01.w;
    __stcs(&orow0[c + 8], o);

    if (p1) {
        float4* orow1 = out + (size_t)e1 * CHUNKS;
        o.x = a10.x - b10.x; o.y = a10.y - b10.y; o.z = a10.z - b10.z; o.w = a10.w - b10.w;
        __stcs(&orow1[c], o);
        o.x = a11.x - b11.x; o.y = a11.y - b11.y; o.z = a11.z - b11.z; o.w = a11.w - b11.w;
        __stcs(&orow1[c + 8], o);
    }
}

// ---------------------------------------------------------------------------
// Launcher. Inputs (metadata order):
//   d_in[0] = M          float32     [E, 64]
//   d_in[1] = edge_index int64/int32 [2, E]  (row0=src, row1=dest)
//   d_in[2] = rev_index  int64/int32 [E]
//   d_in[3] = dim_size   scalar (50000, unused)
// Output: float32 [E, 64]
// ---------------------------------------------------------------------------
extern "C" void kernel_launch(void* const* d_in, const int* in_sizes, int n_in,
                              void* d_out, int out_size) {
    const float4* M4   = (const float4*)d_in[0];
    const void*   ei   = d_in[1];
    const void*   rev  = d_in[2];
    float4*       out4 = (float4*)d_out;

    const int E = in_sizes[2];

    void* mv_ptr = nullptr;
    cudaGetSymbolAddress(&mv_ptr, g_Mv);
    cudaMemsetAsync(mv_ptr, 0, (size_t)N_NODES * CHUNKS * sizeof(float4));

    {
        long long threads = (long long)E * TPE;
        int tpb = 256;
        int blocks = (int)((threads + tpb - 1) / tpb);
        scatter_kernel<<<blocks, tpb>>>(M4, ei, rev, E);
    }
    {
        long long edge_slots = ((long long)E + EPT - 1) / EPT;
        long long threads = edge_slots * TPE;
        int tpb = 256;
        int blocks = (int)((threads + tpb - 1) / tpb);
        gather_kernel<<<blocks, tpb>>>(M4, ei, rev, out4, E);
    }
}